// round 8
// baseline (speedup 1.0000x reference)
#include <cuda_runtime.h>
#include <cstdint>

#define B_ 8
#define T_ 50
#define P_ 1024
#define S_ 128
#define O_ 32
#define H_ 128
#define R_ (B_*P_)
#define NG_ 512
#define K1_ 288
#define K2_ 256
#define KM_ 160

#define TINY_ 1.17549435e-38f
#define LO_   -0.99999994039535522461f
#define SQRT2_ 1.41421356237309504880f

// ---------------- device scratch (static, no runtime allocation) -------------
__device__ float d_h1[R_*S_], d_c1[R_*S_], d_h2[R_*S_], d_c2[R_*S_];
__device__ float d_c1g[R_*S_], d_c2g[R_*S_];
__device__ float d_A1[R_*K1_];   // [noise(128) | obs(32) | h1_gathered(128)]
__device__ float d_A2[R_*K2_];   // [h1_new(128) | h2_gathered(128)]
__device__ float d_Am[R_*KM_];   // [obs(32) | h2_new(128)]
__device__ float d_w[R_];
__device__ int   d_idx[R_];
__device__ float d_Wc1[K1_*NG_]; // gate-interleaved [W1;U1]: col 4s+g <- g*128+s
__device__ float d_Wc2[K2_*NG_]; // gate-interleaved [W2;U2]

// ---------------- cp.async helpers -------------------------------------------
__device__ __forceinline__ uint32_t smem_u32(const void* p) {
    return (uint32_t)__cvta_generic_to_shared(p);
}
#define CP_ASYNC16(dst_u32, src_ptr) \
    asm volatile("cp.async.cg.shared.global [%0], [%1], 16;" :: "r"(dst_u32), "l"(src_ptr))
#define CP_COMMIT()  asm volatile("cp.async.commit_group;")
#define CP_WAIT0()   asm volatile("cp.async.wait_group 0;")

// ---------------- packed f32x2 fma -------------------------------------------
typedef unsigned long long ull_t;
#define FMA2(acc, a2, b2) \
    asm("fma.rn.f32x2 %0, %1, %2, %0;" : "+l"(acc) : "l"(a2), "l"(b2))
#define DUP2(d, f) \
    asm("mov.b64 %0, {%1, %1};" : "=l"(d) : "r"(__float_as_uint(f)))
#define UNPACK2(lo, hi, v) \
    asm("mov.b64 {%0, %1}, %2;" : "=f"(lo), "=f"(hi) : "l"(v))

// ---------------- threefry2x32 (JAX schedule) --------------------------------
__device__ __forceinline__ uint32_t rb32(uint32_t k0, uint32_t k1, uint32_t ctr) {
    uint32_t ks2 = k0 ^ k1 ^ 0x1BD11BDAu;
    uint32_t x0 = 0u + k0, x1 = ctr + k1;
#define TFR_(r) { x0 += x1; x1 = __funnelshift_l(x1, x1, (r)); x1 ^= x0; }
    TFR_(13) TFR_(15) TFR_(26) TFR_(6)
    x0 += k1;  x1 += ks2 + 1u;
    TFR_(17) TFR_(29) TFR_(16) TFR_(24)
    x0 += ks2; x1 += k0 + 2u;
    TFR_(13) TFR_(15) TFR_(26) TFR_(6)
    x0 += k0;  x1 += k1 + 3u;
    TFR_(17) TFR_(29) TFR_(16) TFR_(24)
    x0 += k1;  x1 += ks2 + 4u;
    TFR_(13) TFR_(15) TFR_(26) TFR_(6)
    x0 += ks2; x1 += k0 + 5u;
#undef TFR_
    return x0 ^ x1;
}

// ---------------- XLA-matched math -------------------------------------------
__device__ __forceinline__ float tanh_x(float x) {
    float ax = fabsf(x);
    float xc = fminf(fmaxf(x, -7.90531110763549805f), 7.90531110763549805f);
    float x2 = __fmul_rn(xc, xc);
    float p = -2.76076847742355e-16f;
    p = fmaf(p, x2,  2.00018790482477e-13f);
    p = fmaf(p, x2, -8.60467152213735e-11f);
    p = fmaf(p, x2,  5.12229709037114e-08f);
    p = fmaf(p, x2,  1.48572235717979e-05f);
    p = fmaf(p, x2,  6.37261928875436e-04f);
    p = fmaf(p, x2,  4.89352455891786e-03f);
    float num = __fmul_rn(xc, p);
    float q = 1.19825839466702e-06f;
    q = fmaf(q, x2, 1.18534705686654e-04f);
    q = fmaf(q, x2, 2.26843463243900e-03f);
    q = fmaf(q, x2, 4.89352518554385e-03f);
    return (ax < 0.0004f) ? x : __fdiv_rn(num, q);
}

__device__ __forceinline__ float sig_x(float x) {
    return __fadd_rn(__fmul_rn(0.5f, tanh_x(__fmul_rn(0.5f, x))), 0.5f);
}

__device__ __forceinline__ float erfinv_x(float x) {
    float t = __fmul_rn(x, x);
    float w = -log1pf(-t);
    float p;
    if (w < 5.0f) {
        w = __fadd_rn(w, -2.5f);
        p = 2.81022636e-08f;
        p = __fadd_rn(__fmul_rn(p, w),  3.43273939e-07f);
        p = __fadd_rn(__fmul_rn(p, w), -3.5233877e-06f);
        p = __fadd_rn(__fmul_rn(p, w), -4.39150654e-06f);
        p = __fadd_rn(__fmul_rn(p, w),  0.00021858087f);
        p = __fadd_rn(__fmul_rn(p, w), -0.00125372503f);
        p = __fadd_rn(__fmul_rn(p, w), -0.00417768164f);
        p = __fadd_rn(__fmul_rn(p, w),  0.246640727f);
        p = __fadd_rn(__fmul_rn(p, w),  1.50140941f);
    } else {
        w = __fadd_rn(__fsqrt_rn(w), -3.0f);
        p = -0.000200214257f;
        p = __fadd_rn(__fmul_rn(p, w),  0.000100950558f);
        p = __fadd_rn(__fmul_rn(p, w),  0.00134934322f);
        p = __fadd_rn(__fmul_rn(p, w), -0.00367342844f);
        p = __fadd_rn(__fmul_rn(p, w),  0.00573950773f);
        p = __fadd_rn(__fmul_rn(p, w), -0.0076224613f);
        p = __fadd_rn(__fmul_rn(p, w),  0.00943887047f);
        p = __fadd_rn(__fmul_rn(p, w),  1.00167406f);
        p = __fadd_rn(__fmul_rn(p, w),  2.83297682f);
    }
    return __fmul_rn(p, x);
}

// ---------------- small kernels ----------------------------------------------
__global__ void init_state_kernel() {
    int e = blockIdx.x * 256 + threadIdx.x;
    if (e < R_*S_) { d_h1[e]=0.f; d_c1[e]=0.f; d_h2[e]=0.f; d_c2[e]=0.f; }
    if (e < R_)    { d_w[e] = 1.0f/1024.0f; }
}

__global__ void build_wc_kernel(const float* __restrict__ W1, const float* __restrict__ U1,
                                const float* __restrict__ W2, const float* __restrict__ U2) {
    int i = blockIdx.x * 256 + threadIdx.x;
    if (i < K1_*NG_) {
        int k = i / NG_, c = i % NG_;
        int s = c >> 2, g = c & 3;
        int src = g*128 + s;
        d_Wc1[i] = (k < 160) ? W1[k*NG_ + src] : U1[(k-160)*NG_ + src];
    }
    if (i < K2_*NG_) {
        int k = i / NG_, c = i % NG_;
        int s = c >> 2, g = c & 3;
        int src = g*128 + s;
        d_Wc2[i] = (k < 128) ? W2[k*NG_ + src] : U2[(k-128)*NG_ + src];
    }
}

// categorical resample: idx[b,p] = argmax_j ( gumbel(b,p,j) + w[b,j] )
__global__ void __launch_bounds__(256) resample_kernel(uint32_t k0, uint32_t k1) {
    __shared__ float ws[P_];
    int b = blockIdx.x;
    int tid = threadIdx.x;
    for (int i = tid; i < P_; i += 256) ws[i] = d_w[b*P_ + i];
    __syncthreads();
    int warp = tid >> 5, lane = tid & 31;
    int p = blockIdx.y * 8 + warp;
    uint32_t base = ((uint32_t)(b*P_ + p)) << 10;
    float best = -__int_as_float(0x7f800000);
    int bestj = 0;
    for (int it = 0; it < 32; it++) {
        int j = it*32 + lane;
        uint32_t bits = rb32(k0, k1, base + (uint32_t)j);
        float u01 = __uint_as_float((bits >> 9) | 0x3f800000u) - 1.0f;
        float u = fmaxf(TINY_, __fadd_rn(u01, TINY_));
        float l1 = logf(u);
        float g  = -logf(-l1);
        float v  = __fadd_rn(g, ws[j]);
        if (v > best) { best = v; bestj = j; }
    }
    for (int off = 16; off; off >>= 1) {
        float ov = __shfl_xor_sync(0xffffffffu, best, off);
        int   oj = __shfl_xor_sync(0xffffffffu, bestj, off);
        if (ov > best || (ov == best && oj < bestj)) { best = ov; bestj = oj; }
    }
    if (lane == 0) d_idx[b*P_ + p] = bestj;
}

// gather resampled states, generate noise, build A1 / A2(right) / Am(left)
__global__ void gather_kernel(const float* __restrict__ obs, int t, uint32_t k0, uint32_t k1) {
    int r = blockIdx.x;
    int s = threadIdx.x;
    int b = r >> 10;
    int src = (r & ~1023) + d_idx[r];
    uint32_t bits = rb32(k0, k1, (uint32_t)(r*S_ + s));
    float u01 = __uint_as_float((bits >> 9) | 0x3f800000u) - 1.0f;
    float u = fmaxf(LO_, __fadd_rn(__fmul_rn(u01, 2.0f), LO_));
    float nz = __fmul_rn((float)SQRT2_, erfinv_x(u));
    size_t r1 = (size_t)r * K1_;
    d_A1[r1 + s]        = nz;
    d_A1[r1 + 160 + s]  = d_h1[(size_t)src*S_ + s];
    d_c1g[(size_t)r*S_ + s] = d_c1[(size_t)src*S_ + s];
    d_A2[(size_t)r*K2_ + 128 + s] = d_h2[(size_t)src*S_ + s];
    d_c2g[(size_t)r*S_ + s] = d_c2[(size_t)src*S_ + s];
    if (s < O_) {
        float ov = obs[((size_t)b*T_ + t)*O_ + s];
        d_A1[r1 + 128 + s] = ov;
        d_Am[(size_t)r*KM_ + s] = ov;
    }
}

// ---------------- fused 128x128 GEMM (f32x2) + LSTM, cp.async B, occ-2 -------
#define BM_ 128
#define BN_ 128
#define BK_ 16

template<int K, int LAYER>
__global__ void __launch_bounds__(256, 2) gemm_lstm_kernel(const float* __restrict__ bias,
                                                           float* __restrict__ out, int t) {
    const float* __restrict__ A  = (LAYER == 1) ? d_A1 : d_A2;
    const float* __restrict__ Bw = (LAYER == 1) ? d_Wc1 : d_Wc2;
    const float* __restrict__ Cg = (LAYER == 1) ? d_c1g : d_c2g;

    __shared__ float As[2][BK_][BM_];
    __shared__ float Bs[2][BK_][BN_];

    int tid = threadIdx.x;
    int tx = tid & 15, ty = tid >> 4;
    int rowBase = blockIdx.y * BM_;
    int colBase = blockIdx.x * BN_;

    const int NT = K / BK_;
    // packed accumulators: acc2[i][j2] holds cols (tx*8 + 2*j2, +1) for row ty*8+i
    ull_t acc2[8][4];
    #pragma unroll
    for (int i = 0; i < 8; i++)
        #pragma unroll
        for (int j = 0; j < 4; j++) acc2[i][j] = 0ull;

    // A register staging (transpose into smem); B via cp.async (no transpose)
    float4 ra[2];
    int aAr[2], aAc[2];
    uint32_t bDst[2][2];
    const float* bSrcBase[2];
    #pragma unroll
    for (int l = 0; l < 2; l++) {
        int li = tid*2 + l;
        aAr[l] = li >> 2;  aAc[l] = li & 3;       // A: 128 rows x (4 float4)
        int bkr = li >> 5, bc4 = li & 31;         // B: 16 rows x (32 float4)
        bDst[0][l] = smem_u32(&Bs[0][bkr][bc4*4]);
        bDst[1][l] = smem_u32(&Bs[1][bkr][bc4*4]);
        bSrcBase[l] = &Bw[(size_t)bkr*NG_ + colBase + bc4*4];
    }

    // prologue: stage 0
    #pragma unroll
    for (int l = 0; l < 2; l++) {
        ra[l] = *reinterpret_cast<const float4*>(&A[(size_t)(rowBase + aAr[l])*K + aAc[l]*4]);
        CP_ASYNC16(bDst[0][l], bSrcBase[l]);
    }
    CP_COMMIT();
    #pragma unroll
    for (int l = 0; l < 2; l++) {
        As[0][aAc[l]*4+0][aAr[l]] = ra[l].x;
        As[0][aAc[l]*4+1][aAr[l]] = ra[l].y;
        As[0][aAc[l]*4+2][aAr[l]] = ra[l].z;
        As[0][aAc[l]*4+3][aAr[l]] = ra[l].w;
    }
    CP_WAIT0();
    __syncthreads();

    for (int kt = 0; kt < NT; kt++) {
        int buf = kt & 1;
        if (kt + 1 < NT) {
            int k0 = (kt + 1) * BK_;
            #pragma unroll
            for (int l = 0; l < 2; l++) {
                ra[l] = *reinterpret_cast<const float4*>(&A[(size_t)(rowBase + aAr[l])*K + k0 + aAc[l]*4]);
                CP_ASYNC16(bDst[buf ^ 1][l], bSrcBase[l] + (size_t)k0*NG_);
            }
            CP_COMMIT();
        }
        #pragma unroll
        for (int kk = 0; kk < BK_; kk++) {
            float4 a0 = *reinterpret_cast<const float4*>(&As[buf][kk][ty*8]);
            float4 a1 = *reinterpret_cast<const float4*>(&As[buf][kk][ty*8 + 4]);
            const ull_t* bp = reinterpret_cast<const ull_t*>(&Bs[buf][kk][tx*8]);
            ull_t b0 = bp[0], b1 = bp[1], b2 = bp[2], b3 = bp[3];
            float a[8] = {a0.x, a0.y, a0.z, a0.w, a1.x, a1.y, a1.z, a1.w};
            #pragma unroll
            for (int i = 0; i < 8; i++) {
                ull_t a2; DUP2(a2, a[i]);
                FMA2(acc2[i][0], a2, b0);
                FMA2(acc2[i][1], a2, b1);
                FMA2(acc2[i][2], a2, b2);
                FMA2(acc2[i][3], a2, b3);
            }
        }
        if (kt + 1 < NT) {
            int nb = buf ^ 1;
            #pragma unroll
            for (int l = 0; l < 2; l++) {
                As[nb][aAc[l]*4+0][aAr[l]] = ra[l].x;
                As[nb][aAc[l]*4+1][aAr[l]] = ra[l].y;
                As[nb][aAc[l]*4+2][aAr[l]] = ra[l].z;
                As[nb][aAc[l]*4+3][aAr[l]] = ra[l].w;
            }
            CP_WAIT0();
            __syncthreads();
        }
    }

    // ---------------- LSTM epilogue: 8 rows x 2 complete states --------------
    int row0 = rowBase + ty*8;
    int s0 = (colBase + tx*8) >> 2;
    #pragma unroll
    for (int i = 0; i < 8; i++) {
        int row = row0 + i;
        float z[8];
        #pragma unroll
        for (int j = 0; j < 4; j++) UNPACK2(z[2*j], z[2*j+1], acc2[i][j]);
        #pragma unroll
        for (int u = 0; u < 2; u++) {
            int s = s0 + u;
            float zi = __fadd_rn(z[u*4+0], bias[s]);
            float zf = __fadd_rn(z[u*4+1], bias[128 + s]);
            float zg = __fadd_rn(z[u*4+2], bias[256 + s]);
            float zo = __fadd_rn(z[u*4+3], bias[384 + s]);
            float c  = Cg[(size_t)row*S_ + s];
            float cn = __fadd_rn(__fmul_rn(sig_x(zf), c), __fmul_rn(sig_x(zi), tanh_x(zg)));
            float hn = __fmul_rn(sig_x(zo), tanh_x(cn));
            if (LAYER == 1) {
                d_h1[(size_t)row*S_ + s] = hn;
                d_c1[(size_t)row*S_ + s] = cn;
                d_A2[(size_t)row*K2_ + s] = hn;
            } else {
                d_h2[(size_t)row*S_ + s] = hn;
                d_c2[(size_t)row*S_ + s] = cn;
                d_Am[(size_t)row*KM_ + 32 + s] = hn;
                int b = row >> 10, p = row & 1023;
                out[(((size_t)b*T_ + t)*P_ + p)*129 + s] = hn;
            }
        }
    }
}

// measurement MLP: w = relu([obs|h2] @ Wm1 + bm1) @ Wm2 + bm2
#define MEAS_ROWS 64
#define MEAS_SMEM ((KM_*H_ + H_ + MEAS_ROWS*KM_) * 4)
__global__ void __launch_bounds__(256) meas_kernel(const float* __restrict__ Wm1,
                                                   const float* __restrict__ bm1,
                                                   const float* __restrict__ Wm2,
                                                   const float* __restrict__ bm2,
                                                   float* __restrict__ out, int t) {
    extern __shared__ float sm[];
    float* sW  = sm;
    float* sW2 = sW + KM_*H_;
    float* sR  = sW2 + H_;
    int tid = threadIdx.x;
    int rowBase = blockIdx.x * MEAS_ROWS;
    for (int i = tid; i < KM_*H_; i += 256) sW[i] = Wm1[i];
    if (tid < H_) sW2[tid] = Wm2[tid];
    for (int i = tid; i < MEAS_ROWS*KM_; i += 256) sR[i] = d_Am[(size_t)rowBase*KM_ + i];
    __syncthreads();
    int warp = tid >> 5, lane = tid & 31;
    float b2v = bm2[0];
    for (int rl = warp; rl < MEAS_ROWS; rl += 8) {
        const float* x = sR + rl*KM_;
        float d0 = 0.f, d1 = 0.f, d2 = 0.f, d3 = 0.f;
        #pragma unroll 4
        for (int k = 0; k < KM_; k++) {
            float xv = x[k];
            float4 wv = *reinterpret_cast<const float4*>(&sW[k*H_ + lane*4]);
            d0 = fmaf(xv, wv.x, d0); d1 = fmaf(xv, wv.y, d1);
            d2 = fmaf(xv, wv.z, d2); d3 = fmaf(xv, wv.w, d3);
        }
        int c0 = lane*4;
        d0 = fmaxf(__fadd_rn(d0, bm1[c0+0]), 0.f);
        d1 = fmaxf(__fadd_rn(d1, bm1[c0+1]), 0.f);
        d2 = fmaxf(__fadd_rn(d2, bm1[c0+2]), 0.f);
        d3 = fmaxf(__fadd_rn(d3, bm1[c0+3]), 0.f);
        float acc = fmaf(d3, sW2[c0+3], fmaf(d2, sW2[c0+2], fmaf(d1, sW2[c0+1], __fmul_rn(d0, sW2[c0+0]))));
        for (int off = 16; off; off >>= 1) acc += __shfl_xor_sync(0xffffffffu, acc, off);
        if (lane == 0) {
            float wn = __fadd_rn(acc, b2v);
            int r = rowBase + rl;
            d_w[r] = wn;
            int b = r >> 10, p = r & 1023;
            out[(((size_t)b*T_ + t)*P_ + p)*129 + 128] = wn;
        }
    }
}

// ---------------- host side --------------------------------------------------
static inline uint32_t rotl32_h(uint32_t x, int r) { return (x << r) | (x >> (32 - r)); }
static void tf_host(uint32_t k0, uint32_t k1, uint32_t x0, uint32_t x1,
                    uint32_t* o0, uint32_t* o1) {
    uint32_t ks2 = k0 ^ k1 ^ 0x1BD11BDAu;
    x0 += k0; x1 += k1;
#define HR_(r) { x0 += x1; x1 = rotl32_h(x1, (r)); x1 ^= x0; }
    HR_(13) HR_(15) HR_(26) HR_(6)
    x0 += k1;  x1 += ks2 + 1u;
    HR_(17) HR_(29) HR_(16) HR_(24)
    x0 += ks2; x1 += k0 + 2u;
    HR_(13) HR_(15) HR_(26) HR_(6)
    x0 += k0;  x1 += k1 + 3u;
    HR_(17) HR_(29) HR_(16) HR_(24)
    x0 += k1;  x1 += ks2 + 4u;
    HR_(13) HR_(15) HR_(26) HR_(6)
    x0 += ks2; x1 += k0 + 5u;
#undef HR_
    *o0 = x0; *o1 = x1;
}

extern "C" void kernel_launch(void* const* d_in, const int* in_sizes, int n_in,
                              void* d_out, int out_size) {
    (void)in_sizes; (void)n_in; (void)out_size;
    const float* obs = (const float*)d_in[0];
    const float* W1  = (const float*)d_in[1];
    const float* U1  = (const float*)d_in[2];
    const float* b1  = (const float*)d_in[3];
    const float* W2  = (const float*)d_in[4];
    const float* U2  = (const float*)d_in[5];
    const float* b2  = (const float*)d_in[6];
    const float* Wm1 = (const float*)d_in[7];
    const float* bm1 = (const float*)d_in[8];
    const float* Wm2 = (const float*)d_in[9];
    const float* bm2 = (const float*)d_in[10];
    float* out = (float*)d_out;

    cudaFuncSetAttribute(meas_kernel, cudaFuncAttributeMaxDynamicSharedMemorySize, MEAS_SMEM);

    init_state_kernel<<<(R_*S_ + 255)/256, 256>>>();
    build_wc_kernel<<<(K1_*NG_ + 255)/256, 256>>>(W1, U1, W2, U2);

    uint32_t root0 = 0u, root1 = 42u;
    for (int t = 0; t < T_; t++) {
        uint32_t kt0, kt1, a0, a1, n0, n1;
        tf_host(root0, root1, 0u, (uint32_t)t, &kt0, &kt1);
        tf_host(kt0, kt1, 0u, 0u, &a0, &a1);
        tf_host(kt0, kt1, 0u, 1u, &n0, &n1);

        resample_kernel<<<dim3(B_, P_/8), 256>>>(a0, a1);
        gather_kernel<<<R_, S_>>>(obs, t, n0, n1);
        gemm_lstm_kernel<K1_, 1><<<dim3(NG_/BN_, R_/BM_), 256>>>(b1, nullptr, t);
        gemm_lstm_kernel<K2_, 2><<<dim3(NG_/BN_, R_/BM_), 256>>>(b2, out, t);
        meas_kernel<<<R_/MEAS_ROWS, 256, MEAS_SMEM>>>(Wm1, bm1, Wm2, bm2, out, t);
    }
}

// round 9
// speedup vs baseline: 1.0211x; 1.0211x over previous
#include <cuda_runtime.h>
#include <cstdint>

#define B_ 8
#define T_ 50
#define P_ 1024
#define S_ 128
#define O_ 32
#define H_ 128
#define R_ (B_*P_)
#define NG_ 512
#define K1_ 288
#define K2_ 256
#define KM_ 160

#define TINY_ 1.17549435e-38f
#define LO_   -0.99999994039535522461f
#define SQRT2_ 1.41421356237309504880f

// ---------------- device scratch (static, no runtime allocation) -------------
__device__ float d_h1[R_*S_], d_c1[R_*S_], d_h2[R_*S_], d_c2[R_*S_];
__device__ float d_c1g[R_*S_], d_c2g[R_*S_];
__device__ float d_A1[R_*K1_];   // [noise(128) | obs(32) | h1_gathered(128)]
__device__ float d_A2[R_*K2_];   // [h1_new(128) | h2_gathered(128)]
__device__ float d_Am[R_*KM_];   // [obs(32) | h2_new(128)]
__device__ float d_w[R_];
__device__ int   d_idx[R_];
// tf32-split, mma-fragment-interleaved fused weights
__device__ float d_Wc1h[K1_*NG_], d_Wc1l[K1_*NG_];
__device__ float d_Wc2h[K2_*NG_], d_Wc2l[K2_*NG_];

// ---------------- cp.async helpers -------------------------------------------
__device__ __forceinline__ uint32_t smem_u32(const void* p) {
    return (uint32_t)__cvta_generic_to_shared(p);
}
#define CP_ASYNC16(dst_u32, src_ptr) \
    asm volatile("cp.async.cg.shared.global [%0], [%1], 16;" :: "r"(dst_u32), "l"(src_ptr))
#define CP_COMMIT()  asm volatile("cp.async.commit_group;")
#define CP_WAIT0()   asm volatile("cp.async.wait_group 0;")

// tf32 helpers
__device__ __forceinline__ uint32_t tf32_bits(float a) {
    uint32_t r;
    asm("cvt.rna.tf32.f32 %0, %1;" : "=r"(r) : "f"(a));
    return r;
}

#define MMA_TF32(d, a, b) \
    asm volatile("mma.sync.aligned.m16n8k8.row.col.f32.tf32.tf32.f32 " \
        "{%0,%1,%2,%3}, {%4,%5,%6,%7}, {%8,%9}, {%0,%1,%2,%3};" \
        : "+f"((d)[0]), "+f"((d)[1]), "+f"((d)[2]), "+f"((d)[3]) \
        : "r"((a)[0]), "r"((a)[1]), "r"((a)[2]), "r"((a)[3]), \
          "r"((b)[0]), "r"((b)[1]))

// ---------------- threefry2x32 (JAX schedule) --------------------------------
__device__ __forceinline__ uint32_t rb32(uint32_t k0, uint32_t k1, uint32_t ctr) {
    uint32_t ks2 = k0 ^ k1 ^ 0x1BD11BDAu;
    uint32_t x0 = 0u + k0, x1 = ctr + k1;
#define TFR_(r) { x0 += x1; x1 = __funnelshift_l(x1, x1, (r)); x1 ^= x0; }
    TFR_(13) TFR_(15) TFR_(26) TFR_(6)
    x0 += k1;  x1 += ks2 + 1u;
    TFR_(17) TFR_(29) TFR_(16) TFR_(24)
    x0 += ks2; x1 += k0 + 2u;
    TFR_(13) TFR_(15) TFR_(26) TFR_(6)
    x0 += k0;  x1 += k1 + 3u;
    TFR_(17) TFR_(29) TFR_(16) TFR_(24)
    x0 += k1;  x1 += ks2 + 4u;
    TFR_(13) TFR_(15) TFR_(26) TFR_(6)
    x0 += ks2; x1 += k0 + 5u;
#undef TFR_
    return x0 ^ x1;
}

// ---------------- XLA-matched math -------------------------------------------
__device__ __forceinline__ float tanh_x(float x) {
    float ax = fabsf(x);
    float xc = fminf(fmaxf(x, -7.90531110763549805f), 7.90531110763549805f);
    float x2 = __fmul_rn(xc, xc);
    float p = -2.76076847742355e-16f;
    p = fmaf(p, x2,  2.00018790482477e-13f);
    p = fmaf(p, x2, -8.60467152213735e-11f);
    p = fmaf(p, x2,  5.12229709037114e-08f);
    p = fmaf(p, x2,  1.48572235717979e-05f);
    p = fmaf(p, x2,  6.37261928875436e-04f);
    p = fmaf(p, x2,  4.89352455891786e-03f);
    float num = __fmul_rn(xc, p);
    float q = 1.19825839466702e-06f;
    q = fmaf(q, x2, 1.18534705686654e-04f);
    q = fmaf(q, x2, 2.26843463243900e-03f);
    q = fmaf(q, x2, 4.89352518554385e-03f);
    return (ax < 0.0004f) ? x : __fdiv_rn(num, q);
}

__device__ __forceinline__ float sig_x(float x) {
    return __fadd_rn(__fmul_rn(0.5f, tanh_x(__fmul_rn(0.5f, x))), 0.5f);
}

__device__ __forceinline__ float erfinv_x(float x) {
    float t = __fmul_rn(x, x);
    float w = -log1pf(-t);
    float p;
    if (w < 5.0f) {
        w = __fadd_rn(w, -2.5f);
        p = 2.81022636e-08f;
        p = __fadd_rn(__fmul_rn(p, w),  3.43273939e-07f);
        p = __fadd_rn(__fmul_rn(p, w), -3.5233877e-06f);
        p = __fadd_rn(__fmul_rn(p, w), -4.39150654e-06f);
        p = __fadd_rn(__fmul_rn(p, w),  0.00021858087f);
        p = __fadd_rn(__fmul_rn(p, w), -0.00125372503f);
        p = __fadd_rn(__fmul_rn(p, w), -0.00417768164f);
        p = __fadd_rn(__fmul_rn(p, w),  0.246640727f);
        p = __fadd_rn(__fmul_rn(p, w),  1.50140941f);
    } else {
        w = __fadd_rn(__fsqrt_rn(w), -3.0f);
        p = -0.000200214257f;
        p = __fadd_rn(__fmul_rn(p, w),  0.000100950558f);
        p = __fadd_rn(__fmul_rn(p, w),  0.00134934322f);
        p = __fadd_rn(__fmul_rn(p, w), -0.00367342844f);
        p = __fadd_rn(__fmul_rn(p, w),  0.00573950773f);
        p = __fadd_rn(__fmul_rn(p, w), -0.0076224613f);
        p = __fadd_rn(__fmul_rn(p, w),  0.00943887047f);
        p = __fadd_rn(__fmul_rn(p, w),  1.00167406f);
        p = __fadd_rn(__fmul_rn(p, w),  2.83297682f);
    }
    return __fmul_rn(p, x);
}

// ---------------- small kernels ----------------------------------------------
__global__ void init_state_kernel() {
    int e = blockIdx.x * 256 + threadIdx.x;
    if (e < R_*S_) { d_h1[e]=0.f; d_c1[e]=0.f; d_h2[e]=0.f; d_c2[e]=0.f; }
    if (e < R_)    { d_w[e] = 1.0f/1024.0f; d_idx[e] = 0; }
}

// fragment interleave: global col C -> source gate-major col
// c=C&127: wn=c>>6, r=c&63, u=r>>3, j=(r>>1)&3, v=r&1
// gate g = 2*(u>>2)+v ; state s = (C&~127)/4 + 16*wn + 4*(u&3) + j
__device__ __forceinline__ int src_col_map(int C) {
    int c = C & 127;
    int wn = c >> 6, r = c & 63;
    int u = r >> 3, j = (r >> 1) & 3, v = r & 1;
    int g = 2*(u >> 2) + v;
    int s = ((C & ~127) >> 2) + 16*wn + 4*(u & 3) + j;
    return g*128 + s;
}

__global__ void build_wc_kernel(const float* __restrict__ W1, const float* __restrict__ U1,
                                const float* __restrict__ W2, const float* __restrict__ U2) {
    int i = blockIdx.x * 256 + threadIdx.x;
    if (i < K1_*NG_) {
        int k = i / NG_, C = i % NG_;
        int src = src_col_map(C);
        float wv = (k < 160) ? W1[k*NG_ + src] : U1[(k-160)*NG_ + src];
        uint32_t hb = tf32_bits(wv);
        float hf = __uint_as_float(hb);
        uint32_t lb = tf32_bits(__fadd_rn(wv, -hf));
        d_Wc1h[i] = hf;
        d_Wc1l[i] = __uint_as_float(lb);
    }
    if (i < K2_*NG_) {
        int k = i / NG_, C = i % NG_;
        int src = src_col_map(C);
        float wv = (k < 128) ? W2[k*NG_ + src] : U2[(k-128)*NG_ + src];
        uint32_t hb = tf32_bits(wv);
        float hf = __uint_as_float(hb);
        uint32_t lb = tf32_bits(__fadd_rn(wv, -hf));
        d_Wc2h[i] = hf;
        d_Wc2l[i] = __uint_as_float(lb);
    }
}

// categorical resample: idx[b,p] = argmax_j ( gumbel(b,p,j) + w[b,j] )
__global__ void __launch_bounds__(256) resample_kernel(uint32_t k0, uint32_t k1) {
    __shared__ float ws[P_];
    int b = blockIdx.x;
    int tid = threadIdx.x;
    for (int i = tid; i < P_; i += 256) ws[i] = d_w[b*P_ + i];
    __syncthreads();
    int warp = tid >> 5, lane = tid & 31;
    int p = blockIdx.y * 8 + warp;
    uint32_t base = ((uint32_t)(b*P_ + p)) << 10;
    float best = -__int_as_float(0x7f800000);
    int bestj = 0;
    for (int it = 0; it < 32; it++) {
        int j = it*32 + lane;
        uint32_t bits = rb32(k0, k1, base + (uint32_t)j);
        float u01 = __uint_as_float((bits >> 9) | 0x3f800000u) - 1.0f;
        float u = fmaxf(TINY_, __fadd_rn(u01, TINY_));
        float l1 = logf(u);
        float g  = -logf(-l1);
        float v  = __fadd_rn(g, ws[j]);
        if (v > best) { best = v; bestj = j; }
    }
    for (int off = 16; off; off >>= 1) {
        float ov = __shfl_xor_sync(0xffffffffu, best, off);
        int   oj = __shfl_xor_sync(0xffffffffu, bestj, off);
        if (ov > best || (ov == best && oj < bestj)) { best = ov; bestj = oj; }
    }
    if (lane == 0) d_idx[b*P_ + p] = bestj;
}

// gather resampled states, generate noise, build A1 / A2(right) / Am(left)
__global__ void gather_kernel(const float* __restrict__ obs, int t, uint32_t k0, uint32_t k1) {
    int r = blockIdx.x;
    int s = threadIdx.x;
    int b = r >> 10;
    int src = (r & ~1023) + d_idx[r];
    uint32_t bits = rb32(k0, k1, (uint32_t)(r*S_ + s));
    float u01 = __uint_as_float((bits >> 9) | 0x3f800000u) - 1.0f;
    float u = fmaxf(LO_, __fadd_rn(__fmul_rn(u01, 2.0f), LO_));
    float nz = __fmul_rn((float)SQRT2_, erfinv_x(u));
    size_t r1 = (size_t)r * K1_;
    d_A1[r1 + s]        = nz;
    d_A1[r1 + 160 + s]  = d_h1[(size_t)src*S_ + s];
    d_c1g[(size_t)r*S_ + s] = d_c1[(size_t)src*S_ + s];
    d_A2[(size_t)r*K2_ + 128 + s] = d_h2[(size_t)src*S_ + s];
    d_c2g[(size_t)r*S_ + s] = d_c2[(size_t)src*S_ + s];
    if (s < O_) {
        float ov = obs[((size_t)b*T_ + t)*O_ + s];
        d_A1[r1 + 128 + s] = ov;
        d_Am[(size_t)r*KM_ + s] = ov;
    }
}

// ---------------- 3xTF32 tensor-core GEMM + fused LSTM epilogue --------------
// C[8192,512] = A[8192,K] @ Wc[K,512]; block 128x128; 8 warps (4 M x 2 N);
// warp tile 32x64 -> 2 m16 tiles x 8 n8 tiles; per chunk (k=8): 3 MMAs/tile.
#define BM_ 128
#define BN_ 128
#define CH_ 8
#define PAD_ 136

template<int K, int LAYER>
__global__ void __launch_bounds__(256) gemm_lstm_kernel(const float* __restrict__ bias,
                                                        float* __restrict__ out, int t) {
    const float* __restrict__ A   = (LAYER == 1) ? d_A1 : d_A2;
    const float* __restrict__ Whi = (LAYER == 1) ? d_Wc1h : d_Wc2h;
    const float* __restrict__ Wlo = (LAYER == 1) ? d_Wc1l : d_Wc2l;
    const float* __restrict__ Cg  = (LAYER == 1) ? d_c1g : d_c2g;

    __shared__ float Ah[2][CH_][PAD_], Al[2][CH_][PAD_];
    __shared__ float Bh[2][CH_][PAD_], Bl[2][CH_][PAD_];

    int tid = threadIdx.x;
    int warp = tid >> 5, lane = tid & 31;
    int wm = warp >> 1, wn = warp & 1;
    int q = lane >> 2, j = lane & 3;
    int rowBase = blockIdx.y * BM_;
    int colBase = blockIdx.x * BN_;
    const int NT = K / CH_;

    // A loader: row = tid&127, kq = tid>>7 (two k-quads)
    int ldRow = tid & 127, ldKq = tid >> 7;
    // B loader: kr = tid>>5 (0..7), cc = (tid&31)*4
    int bKr = tid >> 5, bCc = (tid & 31) * 4;
    uint32_t bDstH[2], bDstL[2];
    bDstH[0] = smem_u32(&Bh[0][bKr][bCc]); bDstH[1] = smem_u32(&Bh[1][bKr][bCc]);
    bDstL[0] = smem_u32(&Bl[0][bKr][bCc]); bDstL[1] = smem_u32(&Bl[1][bKr][bCc]);

    float acc[2][8][4];
    #pragma unroll
    for (int a = 0; a < 2; a++)
        #pragma unroll
        for (int u = 0; u < 8; u++)
            #pragma unroll
            for (int x = 0; x < 4; x++) acc[a][u][x] = 0.f;

    float4 av;

    // prologue: chunk 0
    av = *reinterpret_cast<const float4*>(&A[(size_t)(rowBase + ldRow)*K + ldKq*4]);
    CP_ASYNC16(bDstH[0], &Whi[(size_t)bKr*NG_ + colBase + bCc]);
    CP_ASYNC16(bDstL[0], &Wlo[(size_t)bKr*NG_ + colBase + bCc]);
    CP_COMMIT();
    #pragma unroll
    for (int i = 0; i < 4; i++) {
        float a = (&av.x)[i];
        uint32_t hb = tf32_bits(a);
        float hf = __uint_as_float(hb);
        uint32_t lb = tf32_bits(__fadd_rn(a, -hf));
        Ah[0][ldKq*4+i][ldRow] = hf;
        Al[0][ldKq*4+i][ldRow] = __uint_as_float(lb);
    }
    CP_WAIT0();
    __syncthreads();

    for (int kt = 0; kt < NT; kt++) {
        int buf = kt & 1, nb = buf ^ 1;
        if (kt + 1 < NT) {
            int k0 = (kt + 1) * CH_;
            av = *reinterpret_cast<const float4*>(&A[(size_t)(rowBase + ldRow)*K + k0 + ldKq*4]);
            CP_ASYNC16(bDstH[nb], &Whi[(size_t)(k0 + bKr)*NG_ + colBase + bCc]);
            CP_ASYNC16(bDstL[nb], &Wlo[(size_t)(k0 + bKr)*NG_ + colBase + bCc]);
            CP_COMMIT();
        }

        // A fragments (2 m-tiles, hi+lo)
        uint32_t ah[2][4], al[2][4];
        #pragma unroll
        for (int mt = 0; mt < 2; mt++) {
            int r0 = wm*32 + mt*16 + q;
            ah[mt][0] = __float_as_uint(Ah[buf][j][r0]);
            ah[mt][1] = __float_as_uint(Ah[buf][j][r0+8]);
            ah[mt][2] = __float_as_uint(Ah[buf][j+4][r0]);
            ah[mt][3] = __float_as_uint(Ah[buf][j+4][r0+8]);
            al[mt][0] = __float_as_uint(Al[buf][j][r0]);
            al[mt][1] = __float_as_uint(Al[buf][j][r0+8]);
            al[mt][2] = __float_as_uint(Al[buf][j+4][r0]);
            al[mt][3] = __float_as_uint(Al[buf][j+4][r0+8]);
        }
        #pragma unroll
        for (int u = 0; u < 8; u++) {
            int c0 = wn*64 + u*8 + q;
            uint32_t bh[2], bl[2];
            bh[0] = __float_as_uint(Bh[buf][j][c0]);
            bh[1] = __float_as_uint(Bh[buf][j+4][c0]);
            bl[0] = __float_as_uint(Bl[buf][j][c0]);
            bl[1] = __float_as_uint(Bl[buf][j+4][c0]);
            #pragma unroll
            for (int mt = 0; mt < 2; mt++) {
                MMA_TF32(acc[mt][u], ah[mt], bl);
                MMA_TF32(acc[mt][u], al[mt], bh);
                MMA_TF32(acc[mt][u], ah[mt], bh);
            }
        }

        if (kt + 1 < NT) {
            #pragma unroll
            for (int i = 0; i < 4; i++) {
                float a = (&av.x)[i];
                uint32_t hb = tf32_bits(a);
                float hf = __uint_as_float(hb);
                uint32_t lb = tf32_bits(__fadd_rn(a, -hf));
                Ah[nb][ldKq*4+i][ldRow] = hf;
                Al[nb][ldKq*4+i][ldRow] = __uint_as_float(lb);
            }
            CP_WAIT0();
            __syncthreads();
        }
    }

    // ---------------- LSTM epilogue --------------------------------------
    int sBase = (colBase >> 2) + 16*wn;
    #pragma unroll
    for (int mt = 0; mt < 2; mt++) {
        #pragma unroll
        for (int half = 0; half < 2; half++) {
            int row = rowBase + wm*32 + mt*16 + q + half*8;
            #pragma unroll
            for (int ul = 0; ul < 4; ul++) {
                int s = sBase + 4*ul + j;
                float zi = __fadd_rn(acc[mt][ul  ][half*2+0], bias[s]);
                float zf = __fadd_rn(acc[mt][ul  ][half*2+1], bias[128 + s]);
                float zg = __fadd_rn(acc[mt][ul+4][half*2+0], bias[256 + s]);
                float zo = __fadd_rn(acc[mt][ul+4][half*2+1], bias[384 + s]);
                float c  = Cg[(size_t)row*S_ + s];
                float cn = __fadd_rn(__fmul_rn(sig_x(zf), c), __fmul_rn(sig_x(zi), tanh_x(zg)));
                float hn = __fmul_rn(sig_x(zo), tanh_x(cn));
                if (LAYER == 1) {
                    d_h1[(size_t)row*S_ + s] = hn;
                    d_c1[(size_t)row*S_ + s] = cn;
                    d_A2[(size_t)row*K2_ + s] = hn;
                } else {
                    d_h2[(size_t)row*S_ + s] = hn;
                    d_c2[(size_t)row*S_ + s] = cn;
                    d_Am[(size_t)row*KM_ + 32 + s] = hn;
                    int b = row >> 10, p = row & 1023;
                    out[(((size_t)b*T_ + t)*P_ + p)*129 + s] = hn;
                }
            }
        }
    }
}

// measurement MLP: w = relu([obs|h2] @ Wm1 + bm1) @ Wm2 + bm2
#define MEAS_ROWS 64
#define MEAS_SMEM ((KM_*H_ + H_ + MEAS_ROWS*KM_) * 4)
__global__ void __launch_bounds__(256) meas_kernel(const float* __restrict__ Wm1,
                                                   const float* __restrict__ bm1,
                                                   const float* __restrict__ Wm2,
                                                   const float* __restrict__ bm2,
                                                   float* __restrict__ out, int t) {
    extern __shared__ float sm[];
    float* sW  = sm;
    float* sW2 = sW + KM_*H_;
    float* sR  = sW2 + H_;
    int tid = threadIdx.x;
    int rowBase = blockIdx.x * MEAS_ROWS;
    for (int i = tid; i < KM_*H_; i += 256) sW[i] = Wm1[i];
    if (tid < H_) sW2[tid] = Wm2[tid];
    for (int i = tid; i < MEAS_ROWS*KM_; i += 256) sR[i] = d_Am[(size_t)rowBase*KM_ + i];
    __syncthreads();
    int warp = tid >> 5, lane = tid & 31;
    float b2v = bm2[0];
    for (int rl = warp; rl < MEAS_ROWS; rl += 8) {
        const float* x = sR + rl*KM_;
        float d0 = 0.f, d1 = 0.f, d2 = 0.f, d3 = 0.f;
        #pragma unroll 4
        for (int k = 0; k < KM_; k++) {
            float xv = x[k];
            float4 wv = *reinterpret_cast<const float4*>(&sW[k*H_ + lane*4]);
            d0 = fmaf(xv, wv.x, d0); d1 = fmaf(xv, wv.y, d1);
            d2 = fmaf(xv, wv.z, d2); d3 = fmaf(xv, wv.w, d3);
        }
        int c0 = lane*4;
        d0 = fmaxf(__fadd_rn(d0, bm1[c0+0]), 0.f);
        d1 = fmaxf(__fadd_rn(d1, bm1[c0+1]), 0.f);
        d2 = fmaxf(__fadd_rn(d2, bm1[c0+2]), 0.f);
        d3 = fmaxf(__fadd_rn(d3, bm1[c0+3]), 0.f);
        float acc = fmaf(d3, sW2[c0+3], fmaf(d2, sW2[c0+2], fmaf(d1, sW2[c0+1], __fmul_rn(d0, sW2[c0+0]))));
        for (int off = 16; off; off >>= 1) acc += __shfl_xor_sync(0xffffffffu, acc, off);
        if (lane == 0) {
            float wn = __fadd_rn(acc, b2v);
            int r = rowBase + rl;
            d_w[r] = wn;
            int b = r >> 10, p = r & 1023;
            out[(((size_t)b*T_ + t)*P_ + p)*129 + 128] = wn;
        }
    }
}

// ---------------- host side --------------------------------------------------
static inline uint32_t rotl32_h(uint32_t x, int r) { return (x << r) | (x >> (32 - r)); }
static void tf_host(uint32_t k0, uint32_t k1, uint32_t x0, uint32_t x1,
                    uint32_t* o0, uint32_t* o1) {
    uint32_t ks2 = k0 ^ k1 ^ 0x1BD11BDAu;
    x0 += k0; x1 += k1;
#define HR_(r) { x0 += x1; x1 = rotl32_h(x1, (r)); x1 ^= x0; }
    HR_(13) HR_(15) HR_(26) HR_(6)
    x0 += k1;  x1 += ks2 + 1u;
    HR_(17) HR_(29) HR_(16) HR_(24)
    x0 += ks2; x1 += k0 + 2u;
    HR_(13) HR_(15) HR_(26) HR_(6)
    x0 += k0;  x1 += k1 + 3u;
    HR_(17) HR_(29) HR_(16) HR_(24)
    x0 += k1;  x1 += ks2 + 4u;
    HR_(13) HR_(15) HR_(26) HR_(6)
    x0 += ks2; x1 += k0 + 5u;
#undef HR_
    *o0 = x0; *o1 = x1;
}

extern "C" void kernel_launch(void* const* d_in, const int* in_sizes, int n_in,
                              void* d_out, int out_size) {
    (void)in_sizes; (void)n_in; (void)out_size;
    const float* obs = (const float*)d_in[0];
    const float* W1  = (const float*)d_in[1];
    const float* U1  = (const float*)d_in[2];
    const float* b1  = (const float*)d_in[3];
    const float* W2  = (const float*)d_in[4];
    const float* U2  = (const float*)d_in[5];
    const float* b2  = (const float*)d_in[6];
    const float* Wm1 = (const float*)d_in[7];
    const float* bm1 = (const float*)d_in[8];
    const float* Wm2 = (const float*)d_in[9];
    const float* bm2 = (const float*)d_in[10];
    float* out = (float*)d_out;

    cudaFuncSetAttribute(meas_kernel, cudaFuncAttributeMaxDynamicSharedMemorySize, MEAS_SMEM);

    init_state_kernel<<<(R_*S_ + 255)/256, 256>>>();
    build_wc_kernel<<<(K1_*NG_ + 255)/256, 256>>>(W1, U1, W2, U2);

    uint32_t root0 = 0u, root1 = 42u;
    for (int t = 0; t < T_; t++) {
        uint32_t kt0, kt1, a0, a1, n0, n1;
        tf_host(root0, root1, 0u, (uint32_t)t, &kt0, &kt1);
        tf_host(kt0, kt1, 0u, 0u, &a0, &a1);
        tf_host(kt0, kt1, 0u, 1u, &n0, &n1);

        // t=0: all LSTM states are zero, so the resampling gather returns zeros
        // for ANY index vector -> the categorical draw is dead code. d_idx is
        // zeroed in init_state_kernel, keeping gather deterministic.
        if (t > 0)
            resample_kernel<<<dim3(B_, P_/8), 256>>>(a0, a1);
        gather_kernel<<<R_, S_>>>(obs, t, n0, n1);
        gemm_lstm_kernel<K1_, 1><<<dim3(NG_/BN_, R_/BM_), 256>>>(b1, nullptr, t);
        gemm_lstm_kernel<K2_, 2><<<dim3(NG_/BN_, R_/BM_), 256>>>(b2, out, t);
        meas_kernel<<<R_/MEAS_ROWS, 256, MEAS_SMEM>>>(Wm1, bm1, Wm2, bm2, out, t);
    }
}